// round 3
// baseline (speedup 1.0000x reference)
#include <cuda_runtime.h>
#include <cstdint>
#include <math.h>

// Problem dims
#define B_DIM 8192
#define H_DIM 2048
// Combined GEMM K after folding Uc into bottom half of Wc: 2048 (x_t) + 2048 (state)
constexpr int KTOT = 4096;

// GEMM tiling
constexpr int BM = 128;       // rows (batch) per block
constexpr int BN = 64;        // H columns per block (computed for BOTH cand and gate)
constexpr int BK = 16;
constexpr int STAGES = 4;
constexpr int NTHREADS = 256; // 8 warps: 4 along M x 2 along N
constexpr int A_LD = 20;      // 128x16 A tile padded (conflict-free frag loads, 16B aligned rows)
constexpr int B_LD = 68;      // 16x64 B tile padded
constexpr int NITER = KTOT / BK;  // 256

struct SmemStage {
    float A [BM * A_LD];
    float Bc[BK * B_LD];
    float Bg[BK * B_LD];
};

// Scratch (device globals: allocation-free per harness rules)
__device__ float g_Wcc[H_DIM * H_DIM];   // Wc[2048:4096,:] + Uc
__device__ float g_Wgg[H_DIM * H_DIM];   // Wg[2048:4096,:] + Ug
__device__ float g_h  [B_DIM * H_DIM];   // h_new before layernorm

// ---------------------------------------------------------------- helpers
__device__ __forceinline__ void cp_async16(void* dst, const void* src) {
    uint32_t s = (uint32_t)__cvta_generic_to_shared(dst);
    asm volatile("cp.async.cg.shared.global [%0], [%1], 16;" :: "r"(s), "l"(src));
}
__device__ __forceinline__ void cp_commit() {
    asm volatile("cp.async.commit_group;");
}
template<int N> __device__ __forceinline__ void cp_wait() {
    asm volatile("cp.async.wait_group %0;" :: "n"(N));
}
__device__ __forceinline__ uint32_t f2tf32(float f) {
    uint32_t r;
    asm("cvt.rna.tf32.f32 %0, %1;" : "=r"(r) : "f"(f));
    return r;
}
__device__ __forceinline__ void mma8(float* c, const uint32_t* a, uint32_t b0, uint32_t b1) {
    asm volatile(
        "mma.sync.aligned.m16n8k8.row.col.f32.tf32.tf32.f32 "
        "{%0,%1,%2,%3}, {%4,%5,%6,%7}, {%8,%9}, {%0,%1,%2,%3};"
        : "+f"(c[0]), "+f"(c[1]), "+f"(c[2]), "+f"(c[3])
        : "r"(a[0]), "r"(a[1]), "r"(a[2]), "r"(a[3]), "r"(b0), "r"(b1));
}

// ---------------------------------------------------------------- prep: fold Uc/Ug into Wc/Wg bottom halves
__global__ void prep_weights(const float4* __restrict__ Wc_bot, const float4* __restrict__ Uc,
                             const float4* __restrict__ Wg_bot, const float4* __restrict__ Ug) {
    int i = blockIdx.x * blockDim.x + threadIdx.x;   // 0 .. (2048*2048/4 - 1)
    float4 a = Wc_bot[i], b = Uc[i];
    ((float4*)g_Wcc)[i] = make_float4(a.x + b.x, a.y + b.y, a.z + b.z, a.w + b.w);
    float4 c = Wg_bot[i], d = Ug[i];
    ((float4*)g_Wgg)[i] = make_float4(c.x + d.x, c.y + d.y, c.z + d.z, c.w + d.w);
}

// ---------------------------------------------------------------- stage loader
__device__ __forceinline__ void load_stage(
    SmemStage& st, int kt, int tid,
    const float* __restrict__ x_t, const float* __restrict__ state,
    const float* __restrict__ Wc,  const float* __restrict__ Wg,
    int rowBase, int colBase)
{
    int k0 = kt * BK;
    // A tile: 128 rows x 16 k-floats = 512 x 16B chunks
    const float* Asrc; int acol;
    if (k0 < H_DIM) { Asrc = x_t;   acol = k0; }
    else            { Asrc = state; acol = k0 - H_DIM; }
    #pragma unroll
    for (int c = tid; c < 512; c += NTHREADS) {
        int row = c >> 2, kc = (c & 3) * 4;
        cp_async16(&st.A[row * A_LD + kc],
                   Asrc + (size_t)(rowBase + row) * H_DIM + acol + kc);
    }
    // B tiles: 16 k-rows x 64 n-floats each = 256 x 16B chunks each
    const float *Wcsrc, *Wgsrc; int wrow;
    if (k0 < H_DIM) { Wcsrc = Wc;    Wgsrc = Wg;    wrow = k0; }
    else            { Wcsrc = g_Wcc; Wgsrc = g_Wgg; wrow = k0 - H_DIM; }
    {
        int krow = tid >> 4, nc = (tid & 15) * 4;
        const size_t off = (size_t)(wrow + krow) * H_DIM + colBase + nc;
        cp_async16(&st.Bc[krow * B_LD + nc], Wcsrc + off);
        cp_async16(&st.Bg[krow * B_LD + nc], Wgsrc + off);
    }
    cp_commit();
}

// ---------------------------------------------------------------- fused dual-GEMM + gate epilogue
__global__ void __launch_bounds__(NTHREADS, 2)
gemm_kernel(const float* __restrict__ x_t, const float* __restrict__ state,
            const float* __restrict__ Wc,  const float* __restrict__ Wg,
            const float* __restrict__ bc,  const float* __restrict__ bg,
            const float* __restrict__ log_step)
{
    extern __shared__ char smem_raw[];
    SmemStage* smem = (SmemStage*)smem_raw;

    const int rowBase = blockIdx.y * BM;
    const int colBase = blockIdx.x * BN;
    const int tid  = threadIdx.x;
    const int wid  = tid >> 5, lane = tid & 31;
    const int wm   = wid & 3,  wn   = wid >> 2;      // 4 warps along M, 2 along N
    const int g    = lane >> 2, t4  = lane & 3;      // mma group / tid-in-group

    float accC[2][4][4];
    float accG[2][4][4];
    #pragma unroll
    for (int a = 0; a < 2; a++)
        #pragma unroll
        for (int b = 0; b < 4; b++)
            #pragma unroll
            for (int c = 0; c < 4; c++) { accC[a][b][c] = 0.f; accG[a][b][c] = 0.f; }

    // prologue: fill STAGES-1 stages
    for (int s = 0; s < STAGES - 1; s++)
        load_stage(smem[s], s, tid, x_t, state, Wc, Wg, rowBase, colBase);

    for (int kt = 0; kt < NITER; kt++) {
        cp_wait<STAGES - 2>();
        __syncthreads();   // stage kt ready; all warps done with stage (kt-1)

        int nxt = kt + STAGES - 1;
        if (nxt < NITER)
            load_stage(smem[nxt % STAGES], nxt, tid, x_t, state, Wc, Wg, rowBase, colBase);
        else
            cp_commit();   // keep group-count invariant

        SmemStage& st = smem[kt % STAGES];
        #pragma unroll
        for (int kk = 0; kk < 2; kk++) {
            uint32_t af[2][4];
            #pragma unroll
            for (int mt = 0; mt < 2; mt++) {
                const float* Ap = &st.A[(wm * 32 + mt * 16 + g) * A_LD + kk * 8 + t4];
                af[mt][0] = f2tf32(Ap[0]);
                af[mt][1] = f2tf32(Ap[8 * A_LD]);
                af[mt][2] = f2tf32(Ap[4]);
                af[mt][3] = f2tf32(Ap[8 * A_LD + 4]);
            }
            #pragma unroll
            for (int nt = 0; nt < 4; nt++) {
                int n = wn * 32 + nt * 8 + g;
                uint32_t b_c0 = f2tf32(st.Bc[(kk * 8 + t4)     * B_LD + n]);
                uint32_t b_c1 = f2tf32(st.Bc[(kk * 8 + t4 + 4) * B_LD + n]);
                uint32_t b_g0 = f2tf32(st.Bg[(kk * 8 + t4)     * B_LD + n]);
                uint32_t b_g1 = f2tf32(st.Bg[(kk * 8 + t4 + 4) * B_LD + n]);
                #pragma unroll
                for (int mt = 0; mt < 2; mt++) {
                    mma8(accC[mt][nt], af[mt], b_c0, b_c1);
                    mma8(accG[mt][nt], af[mt], b_g0, b_g1);
                }
            }
        }
    }

    // Epilogue: h = alpha*state + (1-alpha)*sigmoid(zg)*tanh(zc)
    #pragma unroll
    for (int nt = 0; nt < 4; nt++) {
        int j0 = colBase + wn * 32 + nt * 8 + 2 * t4;
        float bc0 = bc[j0],  bc1 = bc[j0 + 1];
        float bg0 = bg[j0],  bg1 = bg[j0 + 1];
        float al0 = expf(-expf(-log_step[j0]));       // alpha = exp(-dt/exp(log_step)), dt=1
        float al1 = expf(-expf(-log_step[j0 + 1]));
        #pragma unroll
        for (int mt = 0; mt < 2; mt++) {
            int r0 = rowBase + wm * 32 + mt * 16 + g;
            #pragma unroll
            for (int half = 0; half < 2; half++) {
                int r = r0 + half * 8;
                float zc0 = accC[mt][nt][half * 2]     + bc0;
                float zc1 = accC[mt][nt][half * 2 + 1] + bc1;
                float zg0 = accG[mt][nt][half * 2]     + bg0;
                float zg1 = accG[mt][nt][half * 2 + 1] + bg1;
                float s0 = state[(size_t)r * H_DIM + j0];
                float s1 = state[(size_t)r * H_DIM + j0 + 1];
                float cand0 = tanhf(zc0), cand1 = tanhf(zc1);
                float gate0 = 1.f / (1.f + expf(-zg0));
                float gate1 = 1.f / (1.f + expf(-zg1));
                float h0 = al0 * s0 + (1.f - al0) * gate0 * cand0;
                float h1 = al1 * s1 + (1.f - al1) * gate1 * cand1;
                float2 hv = make_float2(h0, h1);
                *(float2*)&g_h[(size_t)r * H_DIM + j0] = hv;
            }
        }
    }
}

// ---------------------------------------------------------------- layernorm over H=2048
__device__ __forceinline__ float warp_sum(float v) {
    #pragma unroll
    for (int o = 16; o; o >>= 1) v += __shfl_xor_sync(0xffffffffu, v, o);
    return v;
}

__global__ void ln_kernel(const float* __restrict__ gamma, const float* __restrict__ beta,
                          float* __restrict__ out)
{
    int row = blockIdx.x;
    const float4* h = (const float4*)(g_h + (size_t)row * H_DIM);
    float4*       o = (float4*)(out + (size_t)row * H_DIM);
    const float4* gm = (const float4*)gamma;
    const float4* bt = (const float4*)beta;

    int tid = threadIdx.x;           // 256 threads, 2048 floats -> 2 float4 each
    float4 v0 = h[tid], v1 = h[tid + 256];

    float s  = v0.x + v0.y + v0.z + v0.w + v1.x + v1.y + v1.z + v1.w;
    float sq = v0.x*v0.x + v0.y*v0.y + v0.z*v0.z + v0.w*v0.w
             + v1.x*v1.x + v1.y*v1.y + v1.z*v1.z + v1.w*v1.w;

    s  = warp_sum(s);
    sq = warp_sum(sq);
    __shared__ float sh[16];
    int wid = tid >> 5, lane = tid & 31;
    if (lane == 0) { sh[wid] = s; sh[8 + wid] = sq; }
    __syncthreads();
    float tot = 0.f, totq = 0.f;
    #pragma unroll
    for (int i = 0; i < 8; i++) { tot += sh[i]; totq += sh[8 + i]; }

    float mu  = tot * (1.f / H_DIM);
    float var = totq * (1.f / H_DIM) - mu * mu;
    float inv = rsqrtf(var + 1e-5f);

    float4 g0 = gm[tid], g1 = gm[tid + 256];
    float4 b0 = bt[tid], b1 = bt[tid + 256];
    float4 o0, o1;
    o0.x = (v0.x - mu) * inv * g0.x + b0.x;
    o0.y = (v0.y - mu) * inv * g0.y + b0.y;
    o0.z = (v0.z - mu) * inv * g0.z + b0.z;
    o0.w = (v0.w - mu) * inv * g0.w + b0.w;
    o1.x = (v1.x - mu) * inv * g1.x + b1.x;
    o1.y = (v1.y - mu) * inv * g1.y + b1.y;
    o1.z = (v1.z - mu) * inv * g1.z + b1.z;
    o1.w = (v1.w - mu) * inv * g1.w + b1.w;
    o[tid] = o0;
    o[tid + 256] = o1;
}

// ---------------------------------------------------------------- launch
extern "C" void kernel_launch(void* const* d_in, const int* in_sizes, int n_in,
                              void* d_out, int out_size) {
    const float* x_t      = (const float*)d_in[0];
    const float* state    = (const float*)d_in[1];
    const float* Wc       = (const float*)d_in[2];
    const float* Uc       = (const float*)d_in[3];
    const float* bc       = (const float*)d_in[4];
    const float* Wg       = (const float*)d_in[5];
    const float* Ug       = (const float*)d_in[6];
    const float* bg       = (const float*)d_in[7];
    const float* log_step = (const float*)d_in[8];
    const float* gamma    = (const float*)d_in[9];
    const float* beta     = (const float*)d_in[10];
    float* out = (float*)d_out;

    const int smem_bytes = (int)(sizeof(SmemStage) * STAGES);
    cudaFuncSetAttribute(gemm_kernel, cudaFuncAttributeMaxDynamicSharedMemorySize, smem_bytes);

    // Fold recurrent weights: Wcc = Wc[2048:,:] + Uc ; Wgg = Wg[2048:,:] + Ug
    prep_weights<<<(H_DIM * H_DIM / 4) / 256, 256>>>(
        (const float4*)(Wc + (size_t)H_DIM * H_DIM), (const float4*)Uc,
        (const float4*)(Wg + (size_t)H_DIM * H_DIM), (const float4*)Ug);

    dim3 grid(H_DIM / BN, B_DIM / BM);   // (32, 64)
    gemm_kernel<<<grid, NTHREADS, smem_bytes>>>(x_t, state, Wc, Wg, bc, bg, log_step);

    ln_kernel<<<B_DIM, 256>>>(gamma, beta, out);
}

// round 6
// speedup vs baseline: 1.2168x; 1.2168x over previous
#include <cuda_runtime.h>
#include <cstdint>
#include <math.h>

// ---------------------------------------------------------------- dims
#define B_DIM 8192
#define H_DIM 2048
constexpr int KTOT = 4096;            // folded K: 2048 (x_t) + 2048 (state)

// GEMM tiling
constexpr int BM = 128;               // batch rows per CTA
constexpr int BN = 128;               // H cols per CTA (both cand & gate computed)
constexpr int BK = 16;
constexpr int STAGES = 4;
constexpr int NTHREADS = 256;         // 8 warps: 2 along M x 4 along N; warp tile 64x32
constexpr int NITER = KTOT / BK;      // 256
constexpr int A_LD = 20;              // 128x16 A tile, padded rows (80B, 16B-aligned, conflict-free)
constexpr int B_LD = 136;             // 16x128 B tile, padded rows (544B, conflict-free: t4*136%32=8*t4)

struct SmemStage {
    float A [BM * A_LD];              // 2560 floats
    float Bc[BK * B_LD];              // 2176
    float Bg[BK * B_LD];              // 2176
};
constexpr int SMEM_TOTAL = (int)(sizeof(SmemStage) * STAGES);   // 110592 B

// ---------------------------------------------------------------- scratch (device globals)
__device__ float g_Wcf[(size_t)KTOT * H_DIM];   // rna( Wc[k][j] + (k>=2048 ? Uc[k-2048][j] : 0) )
__device__ float g_Wgf[(size_t)KTOT * H_DIM];   // same for gate
__device__ float g_xr [(size_t)B_DIM * H_DIM];  // rna(x_t)
__device__ float g_sr [(size_t)B_DIM * H_DIM];  // rna(state)
__device__ float g_h  [(size_t)B_DIM * H_DIM];  // h_new before layernorm

// ---------------------------------------------------------------- helpers
__device__ __forceinline__ void cp_async16(void* dst, const void* src) {
    uint32_t s = (uint32_t)__cvta_generic_to_shared(dst);
    asm volatile("cp.async.cg.shared.global [%0], [%1], 16;" :: "r"(s), "l"(src));
}
__device__ __forceinline__ void cp_commit() { asm volatile("cp.async.commit_group;"); }
template<int N> __device__ __forceinline__ void cp_wait() {
    asm volatile("cp.async.wait_group %0;" :: "n"(N));
}
__device__ __forceinline__ uint32_t f2tf32(float f) {
    uint32_t r; asm("cvt.rna.tf32.f32 %0, %1;" : "=r"(r) : "f"(f)); return r;
}
__device__ __forceinline__ void mma8(float* c, const uint32_t* a, uint32_t b0, uint32_t b1) {
    asm volatile(
        "mma.sync.aligned.m16n8k8.row.col.f32.tf32.tf32.f32 "
        "{%0,%1,%2,%3}, {%4,%5,%6,%7}, {%8,%9}, {%0,%1,%2,%3};"
        : "+f"(c[0]), "+f"(c[1]), "+f"(c[2]), "+f"(c[3])
        : "r"(a[0]), "r"(a[1]), "r"(a[2]), "r"(a[3]), "r"(b0), "r"(b1));
}

// ---------------------------------------------------------------- prep: fold + tf32-round weights
// g_Wf[k][j] = rna( W[k][j] + (k>=2048 ? U[k-2048][j] : 0) )
__global__ void prep_weights(const float4* __restrict__ Wc, const float4* __restrict__ Uc,
                             const float4* __restrict__ Wg, const float4* __restrict__ Ug) {
    size_t i = (size_t)blockIdx.x * blockDim.x + threadIdx.x;   // over KTOT*H/4
    constexpr size_t HALF = (size_t)H_DIM * H_DIM / 4;          // fold threshold in float4s
    float4 a = Wc[i], c = Wg[i];
    if (i >= HALF) {
        float4 b = Uc[i - HALF], d = Ug[i - HALF];
        a.x += b.x; a.y += b.y; a.z += b.z; a.w += b.w;
        c.x += d.x; c.y += d.y; c.z += d.z; c.w += d.w;
    }
    float4 ra, rc;
    ra.x = __uint_as_float(f2tf32(a.x)); ra.y = __uint_as_float(f2tf32(a.y));
    ra.z = __uint_as_float(f2tf32(a.z)); ra.w = __uint_as_float(f2tf32(a.w));
    rc.x = __uint_as_float(f2tf32(c.x)); rc.y = __uint_as_float(f2tf32(c.y));
    rc.z = __uint_as_float(f2tf32(c.z)); rc.w = __uint_as_float(f2tf32(c.w));
    ((float4*)g_Wcf)[i] = ra;
    ((float4*)g_Wgf)[i] = rc;
}

// tf32-round activations
__global__ void prep_act(const float4* __restrict__ x_t, const float4* __restrict__ state) {
    size_t i = (size_t)blockIdx.x * blockDim.x + threadIdx.x;   // over B*H/4
    float4 a = x_t[i], b = state[i];
    float4 ra, rb;
    ra.x = __uint_as_float(f2tf32(a.x)); ra.y = __uint_as_float(f2tf32(a.y));
    ra.z = __uint_as_float(f2tf32(a.z)); ra.w = __uint_as_float(f2tf32(a.w));
    rb.x = __uint_as_float(f2tf32(b.x)); rb.y = __uint_as_float(f2tf32(b.y));
    rb.z = __uint_as_float(f2tf32(b.z)); rb.w = __uint_as_float(f2tf32(b.w));
    ((float4*)g_xr)[i] = ra;
    ((float4*)g_sr)[i] = rb;
}

// ---------------------------------------------------------------- stage loader
__device__ __forceinline__ void load_stage(
    SmemStage& st, int ks, int tid, int rowBase, int colBase)
{
    const int k0 = ks * BK;
    const float* Asrc; int ka;
    if (k0 < H_DIM) { Asrc = g_xr; ka = k0; }
    else            { Asrc = g_sr; ka = k0 - H_DIM; }
    // A: 128 rows x 16 floats = 512 x 16B chunks
    #pragma unroll
    for (int i = 0; i < 2; i++) {
        int c = tid + i * NTHREADS;
        int row = c >> 2, ch = (c & 3) * 4;
        cp_async16(&st.A[row * A_LD + ch],
                   Asrc + (size_t)(rowBase + row) * H_DIM + ka + ch);
    }
    // Bc / Bg: 16 k-rows x 128 floats = 512 x 16B chunks each
    #pragma unroll
    for (int i = 0; i < 2; i++) {
        int c = tid + i * NTHREADS;
        int kr = c >> 5, ch = (c & 31) * 4;
        size_t off = (size_t)(k0 + kr) * H_DIM + colBase + ch;
        cp_async16(&st.Bc[kr * B_LD + ch], g_Wcf + off);
        cp_async16(&st.Bg[kr * B_LD + ch], g_Wgf + off);
    }
    cp_commit();
}

// ---------------------------------------------------------------- fused dual-GEMM + gate epilogue
__global__ void __launch_bounds__(NTHREADS, 1)
gemm_kernel(const float* __restrict__ state,
            const float* __restrict__ bc,  const float* __restrict__ bg,
            const float* __restrict__ log_step)
{
    extern __shared__ char smem_raw[];
    SmemStage* smem = (SmemStage*)smem_raw;

    const int rowBase = blockIdx.y * BM;
    const int colBase = blockIdx.x * BN;
    const int tid  = threadIdx.x;
    const int wid  = tid >> 5, lane = tid & 31;
    const int wm   = wid & 1,  wn   = wid >> 1;      // 2 warps along M, 4 along N
    const int g    = lane >> 2, t4  = lane & 3;

    float accC[4][4][4];     // [mt][nt][frag]
    float accG[4][4][4];
    #pragma unroll
    for (int a = 0; a < 4; a++)
        #pragma unroll
        for (int b = 0; b < 4; b++)
            #pragma unroll
            for (int c = 0; c < 4; c++) { accC[a][b][c] = 0.f; accG[a][b][c] = 0.f; }

    for (int s = 0; s < STAGES - 1; s++)
        load_stage(smem[s], s, tid, rowBase, colBase);

    for (int kt = 0; kt < NITER; kt++) {
        cp_wait<STAGES - 2>();
        __syncthreads();                         // stage kt ready; stage kt-1 fully consumed

        int nxt = kt + STAGES - 1;
        if (nxt < NITER)
            load_stage(smem[nxt % STAGES], nxt, tid, rowBase, colBase);
        else
            cp_commit();                         // keep group-count invariant

        SmemStage& st = smem[kt % STAGES];
        #pragma unroll
        for (int kk = 0; kk < 2; kk++) {
            uint32_t af[4][4];
            #pragma unroll
            for (int mt = 0; mt < 4; mt++) {
                const float* Ap = &st.A[(wm * 64 + mt * 16 + g) * A_LD + kk * 8 + t4];
                af[mt][0] = __float_as_uint(Ap[0]);
                af[mt][1] = __float_as_uint(Ap[8 * A_LD]);
                af[mt][2] = __float_as_uint(Ap[4]);
                af[mt][3] = __float_as_uint(Ap[8 * A_LD + 4]);
            }
            #pragma unroll
            for (int nt = 0; nt < 4; nt++) {
                int n = wn * 32 + nt * 8 + g;
                uint32_t b_c0 = __float_as_uint(st.Bc[(kk * 8 + t4)     * B_LD + n]);
                uint32_t b_c1 = __float_as_uint(st.Bc[(kk * 8 + t4 + 4) * B_LD + n]);
                uint32_t b_g0 = __float_as_uint(st.Bg[(kk * 8 + t4)     * B_LD + n]);
                uint32_t b_g1 = __float_as_uint(st.Bg[(kk * 8 + t4 + 4) * B_LD + n]);
                #pragma unroll
                for (int mt = 0; mt < 4; mt++) {
                    mma8(accC[mt][nt], af[mt], b_c0, b_c1);
                    mma8(accG[mt][nt], af[mt], b_g0, b_g1);
                }
            }
        }
    }

    // Epilogue: h = alpha*state + (1-alpha)*sigmoid(zg)*tanh(zc)
    #pragma unroll
    for (int nt = 0; nt < 4; nt++) {
        int j0 = colBase + wn * 32 + nt * 8 + 2 * t4;
        float bc0 = bc[j0],  bc1 = bc[j0 + 1];
        float bg0 = bg[j0],  bg1 = bg[j0 + 1];
        float al0 = expf(-expf(-log_step[j0]));      // alpha = exp(-1/exp(log_step))
        float al1 = expf(-expf(-log_step[j0 + 1]));
        #pragma unroll
        for (int mt = 0; mt < 4; mt++) {
            int r0 = rowBase + wm * 64 + mt * 16 + g;
            #pragma unroll
            for (int half = 0; half < 2; half++) {
                int r = r0 + half * 8;
                float zc0 = accC[mt][nt][half * 2]     + bc0;
                float zc1 = accC[mt][nt][half * 2 + 1] + bc1;
                float zg0 = accG[mt][nt][half * 2]     + bg0;
                float zg1 = accG[mt][nt][half * 2 + 1] + bg1;
                float s0 = state[(size_t)r * H_DIM + j0];
                float s1 = state[(size_t)r * H_DIM + j0 + 1];
                float cand0 = tanhf(zc0), cand1 = tanhf(zc1);
                float gate0 = 1.f / (1.f + expf(-zg0));
                float gate1 = 1.f / (1.f + expf(-zg1));
                float h0 = al0 * s0 + (1.f - al0) * gate0 * cand0;
                float h1 = al1 * s1 + (1.f - al1) * gate1 * cand1;
                *(float2*)&g_h[(size_t)r * H_DIM + j0] = make_float2(h0, h1);
            }
        }
    }
}

// ---------------------------------------------------------------- layernorm over H=2048
__device__ __forceinline__ float warp_sum(float v) {
    #pragma unroll
    for (int o = 16; o; o >>= 1) v += __shfl_xor_sync(0xffffffffu, v, o);
    return v;
}

__global__ void ln_kernel(const float* __restrict__ gamma, const float* __restrict__ beta,
                          float* __restrict__ out)
{
    int row = blockIdx.x;
    const float4* h = (const float4*)(g_h + (size_t)row * H_DIM);
    float4*       o = (float4*)(out + (size_t)row * H_DIM);
    const float4* gm = (const float4*)gamma;
    const float4* bt = (const float4*)beta;

    int tid = threadIdx.x;
    float4 v0 = h[tid], v1 = h[tid + 256];

    float s  = v0.x + v0.y + v0.z + v0.w + v1.x + v1.y + v1.z + v1.w;
    float sq = v0.x*v0.x + v0.y*v0.y + v0.z*v0.z + v0.w*v0.w
             + v1.x*v1.x + v1.y*v1.y + v1.z*v1.z + v1.w*v1.w;

    s  = warp_sum(s);
    sq = warp_sum(sq);
    __shared__ float sh[16];
    int wid = tid >> 5, lane = tid & 31;
    if (lane == 0) { sh[wid] = s; sh[8 + wid] = sq; }
    __syncthreads();
    float tot = 0.f, totq = 0.f;
    #pragma unroll
    for (int i = 0; i < 8; i++) { tot += sh[i]; totq += sh[8 + i]; }

    float mu  = tot * (1.f / H_DIM);
    float var = totq * (1.f / H_DIM) - mu * mu;
    float inv = rsqrtf(var + 1e-5f);

    float4 g0 = gm[tid], g1 = gm[tid + 256];
    float4 b0 = bt[tid], b1 = bt[tid + 256];
    float4 o0, o1;
    o0.x = (v0.x - mu) * inv * g0.x + b0.x;
    o0.y = (v0.y - mu) * inv * g0.y + b0.y;
    o0.z = (v0.z - mu) * inv * g0.z + b0.z;
    o0.w = (v0.w - mu) * inv * g0.w + b0.w;
    o1.x = (v1.x - mu) * inv * g1.x + b1.x;
    o1.y = (v1.y - mu) * inv * g1.y + b1.y;
    o1.z = (v1.z - mu) * inv * g1.z + b1.z;
    o1.w = (v1.w - mu) * inv * g1.w + b1.w;
    o[tid] = o0;
    o[tid + 256] = o1;
}

// ---------------------------------------------------------------- launch
extern "C" void kernel_launch(void* const* d_in, const int* in_sizes, int n_in,
                              void* d_out, int out_size) {
    const float* x_t      = (const float*)d_in[0];
    const float* state    = (const float*)d_in[1];
    const float* Wc       = (const float*)d_in[2];
    const float* Uc       = (const float*)d_in[3];
    const float* bc       = (const float*)d_in[4];
    const float* Wg       = (const float*)d_in[5];
    const float* Ug       = (const float*)d_in[6];
    const float* bg       = (const float*)d_in[7];
    const float* log_step = (const float*)d_in[8];
    const float* gamma    = (const float*)d_in[9];
    const float* beta     = (const float*)d_in[10];
    float* out = (float*)d_out;

    cudaFuncSetAttribute(gemm_kernel, cudaFuncAttributeMaxDynamicSharedMemorySize, SMEM_TOTAL);

    prep_weights<<<(int)(((size_t)KTOT * H_DIM / 4) / 256), 256>>>(
        (const float4*)Wc, (const float4*)Uc, (const float4*)Wg, (const float4*)Ug);
    prep_act<<<(int)(((size_t)B_DIM * H_DIM / 4) / 256), 256>>>(
        (const float4*)x_t, (const float4*)state);

    dim3 grid(H_DIM / BN, B_DIM / BM);     // (16, 64) = 1024 CTAs
    gemm_kernel<<<grid, NTHREADS, SMEM_TOTAL>>>(state, bc, bg, log_step);

    ln_kernel<<<B_DIM, 256>>>(gamma, beta, out);
}